// round 2
// baseline (speedup 1.0000x reference)
#include <cuda_runtime.h>
#include <math.h>

#define HID 2048
#define BATCH 512
#define SEQ 128
#define NCLS 10

// Ping-pong hidden-state scratch (device globals: allocation-free).
__device__ float g_h[2][HID * BATCH];

#define BM 128
#define BN 64
#define BK 16
#define TM 8
#define TN 4
// 256 threads: 16 row-groups x 16 col-groups

// Step 0: h = tanh(whx * x[:,0] + bh)   (h_prev = 0 so no GEMM)
__global__ __launch_bounds__(256) void rnn_init(
    const float* __restrict__ whx, const float* __restrict__ bh,
    const float* __restrict__ x)
{
    int idx = blockIdx.x * blockDim.x + threadIdx.x;
    if (idx >= HID * BATCH) return;
    int i = idx / BATCH;
    int b = idx % BATCH;
    g_h[0][idx] = tanhf(whx[i] * x[b * SEQ + 0] + bh[i]);
}

// Steps 1..127: h_new = tanh(whh @ h + whx * x[:,t] + bh)
__global__ __launch_bounds__(256) void rnn_step(
    const float* __restrict__ whh, const float* __restrict__ whx,
    const float* __restrict__ bh, const float* __restrict__ x,
    int t, int src, int dst)
{
    __shared__ float As[BK][BM + 4];  // transposed whh tile, padded
    __shared__ float Bs[BK][BN];      // h tile
    __shared__ float xs[BN];          // x[:, t] slice for this column tile

    const float* __restrict__ hin = g_h[src];
    float* __restrict__ hout = g_h[dst];

    int tid = threadIdx.x;
    int brow = blockIdx.y * BM;   // hidden-row tile base
    int bcol = blockIdx.x * BN;   // batch-col tile base

    if (tid < BN) xs[tid] = x[(bcol + tid) * SEQ + t];

    int ty = tid / 16;   // 0..15 -> row group (TM rows each)
    int tx = tid % 16;   // 0..15 -> col group (TN cols each)

    float acc[TM][TN];
#pragma unroll
    for (int i = 0; i < TM; i++)
#pragma unroll
        for (int j = 0; j < TN; j++) acc[i][j] = 0.f;

    // A-load mapping: 512 float4 per tile (128 rows x 4 float4-cols), 2 per thread
    int a_row = tid / 4;     // 0..63
    int a_c4 = tid % 4;      // 0..3 (which float4 of the 16-wide k-slab)
    // B-load mapping: 256 float4 per tile (16 k x 16 float4-cols), 1 per thread
    int b_k = tid / 16;      // 0..15
    int b_b4 = tid % 16;     // 0..15

    for (int k0 = 0; k0 < HID; k0 += BK) {
#pragma unroll
        for (int r = 0; r < 2; r++) {
            int row = a_row + r * 64;
            float4 v = *(const float4*)&whh[(size_t)(brow + row) * HID + k0 + a_c4 * 4];
            As[a_c4 * 4 + 0][row] = v.x;
            As[a_c4 * 4 + 1][row] = v.y;
            As[a_c4 * 4 + 2][row] = v.z;
            As[a_c4 * 4 + 3][row] = v.w;
        }
        float4 bv = *(const float4*)&hin[(size_t)(k0 + b_k) * BATCH + bcol + b_b4 * 4];
        *(float4*)&Bs[b_k][b_b4 * 4] = bv;
        __syncthreads();

#pragma unroll
        for (int kk = 0; kk < BK; kk++) {
            float a[TM], b[TN];
#pragma unroll
            for (int i = 0; i < TM; i++) a[i] = As[kk][ty * TM + i];
#pragma unroll
            for (int j = 0; j < TN; j++) b[j] = Bs[kk][tx * TN + j];
#pragma unroll
            for (int i = 0; i < TM; i++)
#pragma unroll
                for (int j = 0; j < TN; j++)
                    acc[i][j] = fmaf(a[i], b[j], acc[i][j]);
        }
        __syncthreads();
    }

#pragma unroll
    for (int i = 0; i < TM; i++) {
        int row = brow + ty * TM + i;
        float wx = whx[row];
        float bb = bh[row];
#pragma unroll
        for (int j = 0; j < TN; j++) {
            int lc = tx * TN + j;
            float v = acc[i][j] + wx * xs[lc] + bb;
            hout[(size_t)row * BATCH + bcol + lc] = tanhf(v);
        }
    }
}

// Final projection: out[b, c] = wph[c,:] . h[:, b] + bp[c]
__global__ __launch_bounds__(256) void rnn_proj(
    const float* __restrict__ wph, const float* __restrict__ bp,
    float* __restrict__ out, int src)
{
    const float* __restrict__ h = g_h[src];
    int b = blockIdx.x;
    int tid = threadIdx.x;

    float part[NCLS];
#pragma unroll
    for (int c = 0; c < NCLS; c++) part[c] = 0.f;

    for (int k = tid; k < HID; k += 256) {
        float hv = h[(size_t)k * BATCH + b];
#pragma unroll
        for (int c = 0; c < NCLS; c++)
            part[c] = fmaf(wph[c * HID + k], hv, part[c]);
    }

    __shared__ float red[256];
    for (int c = 0; c < NCLS; c++) {
        red[tid] = part[c];
        __syncthreads();
        for (int s = 128; s > 0; s >>= 1) {
            if (tid < s) red[tid] += red[tid + s];
            __syncthreads();
        }
        if (tid == 0) out[b * NCLS + c] = red[0] + bp[c];
        __syncthreads();
    }
}

extern "C" void kernel_launch(void* const* d_in, const int* in_sizes, int n_in,
                              void* d_out, int out_size) {
    const float* x = (const float*)d_in[0];      // [512, 128]
    const float* whx = (const float*)d_in[1];    // [2048, 1]
    const float* whh = (const float*)d_in[2];    // [2048, 2048]
    const float* bh = (const float*)d_in[3];     // [2048, 1]
    const float* wph = (const float*)d_in[4];    // [10, 2048]
    const float* bp = (const float*)d_in[5];     // [10, 1]
    float* out = (float*)d_out;                  // [512, 10]

    (void)in_sizes; (void)n_in; (void)out_size;

    // t = 0 (h_prev = 0): writes g_h[0]
    rnn_init<<<(HID * BATCH + 255) / 256, 256>>>(whx, bh, x);

    // t = 1..127: read g_h[(t-1)&1], write g_h[t&1]
    dim3 grid(BATCH / BN, HID / BM);  // (8, 16) = 128 blocks
    for (int t = 1; t < SEQ; t++) {
        rnn_step<<<grid, 256>>>(whh, whx, bh, x, t, (t - 1) & 1, t & 1);
    }

    // final h lives in g_h[(SEQ-1)&1] = g_h[1]
    rnn_proj<<<BATCH, 256>>>(wph, bp, out, (SEQ - 1) & 1);
}

// round 4
// speedup vs baseline: 4.2592x; 4.2592x over previous
#include <cuda_runtime.h>
#include <cuda_bf16.h>
#include <math.h>
#include <stdint.h>

#define HID 2048
#define BATCH 512
#define SEQ 128
#define NCLS 10

#define BM 128            // batch rows per CTA
#define BN 64             // hidden cols per CTA
#define KS 64             // k elements per slab
#define NSLAB (HID / KS)  // 32

// ---- device globals (allocation-free scratch) ----
__device__ __nv_bfloat16 g_hTh[2][BATCH * HID];   // hidden hi, [B][K] row-major
__device__ __nv_bfloat16 g_hTl[2][BATCH * HID];   // hidden lo
__device__ __nv_bfloat16 g_Wh[HID * HID];         // whh hi, [N][K] row-major
__device__ __nv_bfloat16 g_Wl[HID * HID];         // whh lo

// ---- SMEM layout (dynamic) ----
#define SM_XS   0                 // 128 f32
#define SM_WHX  512               // 64 f32
#define SM_BH   768               // 64 f32
#define SM_SLAB 1024
#define AH_OFF  0                 // 128 rows x 128B
#define AL_OFF  16384
#define WH_OFF  32768             // 64 rows x 128B
#define WL_OFF  40960
#define STAGE_SZ 49152
#define SMEM_TOTAL (SM_SLAB + 2 * STAGE_SZ)   // 99328

__device__ __forceinline__ uint32_t smem_u32(const void* p) {
    uint32_t a;
    asm("{ .reg .u64 t; cvta.to.shared.u64 t, %1; cvt.u32.u64 %0, t; }" : "=r"(a) : "l"(p));
    return a;
}
__device__ __forceinline__ void cp16(uint32_t saddr, const void* g) {
    asm volatile("cp.async.cg.shared.global [%0], [%1], 16;" :: "r"(saddr), "l"(g));
}
#define CP_COMMIT() asm volatile("cp.async.commit_group;" ::: "memory")
#define CP_WAIT(n)  asm volatile("cp.async.wait_group %0;" :: "n"(n) : "memory")

#define LDSM_X4(d0, d1, d2, d3, a) \
    asm volatile("ldmatrix.sync.aligned.m8n8.x4.shared.b16 {%0,%1,%2,%3}, [%4];" \
        : "=r"(d0), "=r"(d1), "=r"(d2), "=r"(d3) : "r"(a))

#define MMA16816(c0, c1, c2, c3, a0, a1, a2, a3, b0, b1) \
    asm volatile("mma.sync.aligned.m16n8k16.row.col.f32.bf16.bf16.f32 " \
        "{%0,%1,%2,%3}, {%4,%5,%6,%7}, {%8,%9}, {%0,%1,%2,%3};" \
        : "+f"(c0), "+f"(c1), "+f"(c2), "+f"(c3) \
        : "r"(a0), "r"(a1), "r"(a2), "r"(a3), "r"(b0), "r"(b1))

// ================= one-time prep =================
__global__ __launch_bounds__(256) void convert_w(const float* __restrict__ whh) {
    int i = blockIdx.x * blockDim.x + threadIdx.x;
    if (i >= HID * HID) return;
    float w = whh[i];
    __nv_bfloat16 hi = __float2bfloat16(w);
    g_Wh[i] = hi;
    g_Wl[i] = __float2bfloat16(w - __bfloat162float(hi));
}

__global__ __launch_bounds__(256) void rnn_init(
    const float* __restrict__ whx, const float* __restrict__ bh, const float* __restrict__ x) {
    int i = blockIdx.x * blockDim.x + threadIdx.x;
    if (i >= BATCH * HID) return;
    int b = i / HID, m = i - b * HID;
    float v = tanhf(whx[m] * x[b * SEQ + 0] + bh[m]);
    __nv_bfloat16 hi = __float2bfloat16(v);
    g_hTh[0][i] = hi;
    g_hTl[0][i] = __float2bfloat16(v - __bfloat162float(hi));
}

// ================= per-step GEMM: hT_new = tanh(hT @ W^T + whx*x_t + bh) =================
__global__ __launch_bounds__(256, 1) void rnn_step_mma(
    const float* __restrict__ x, const float* __restrict__ whx,
    const float* __restrict__ bh, int t, int src, int dst)
{
    extern __shared__ char smem[];
    uint32_t sb = smem_u32(smem);
    int tid = threadIdx.x, wid = tid >> 5, lane = tid & 31;
    int wm = wid >> 1, wn = wid & 1;      // warp tile: 32(m) x 32(n), 4x2 warps
    int n0  = blockIdx.x * BN;            // hidden col base
    int bt0 = blockIdx.y * BM;            // batch row base

    if (tid < 128) ((float*)(smem + SM_XS))[tid] = x[(bt0 + tid) * SEQ + t];
    else if (tid < 192) ((float*)(smem + SM_WHX))[tid - 128] = whx[n0 + tid - 128];
    else ((float*)(smem + SM_BH))[tid - 192] = bh[n0 + tid - 192];

    const __nv_bfloat16* Ah = g_hTh[src] + (size_t)bt0 * HID;
    const __nv_bfloat16* Al = g_hTl[src] + (size_t)bt0 * HID;
    const __nv_bfloat16* Wh = g_Wh + (size_t)n0 * HID;
    const __nv_bfloat16* Wl = g_Wl + (size_t)n0 * HID;

    float c[2][4][4];
#pragma unroll
    for (int i = 0; i < 2; i++)
#pragma unroll
        for (int j = 0; j < 4; j++)
#pragma unroll
            for (int q = 0; q < 4; q++) c[i][j][q] = 0.f;

#define LOAD_SLAB(stage, ks) do {                                              \
        uint32_t sbase = sb + SM_SLAB + (stage) * STAGE_SZ;                    \
        _Pragma("unroll")                                                      \
        for (int i = 0; i < 4; i++) {                                          \
            int idx = tid + 256 * i; int m = idx >> 3; int cc = idx & 7;       \
            uint32_t so = (uint32_t)(m * 128) + (uint32_t)((cc ^ (m & 7)) << 4); \
            size_t go = (size_t)m * HID + (ks) * KS + cc * 8;                  \
            cp16(sbase + AH_OFF + so, Ah + go);                                \
            cp16(sbase + AL_OFF + so, Al + go);                                \
        }                                                                      \
        _Pragma("unroll")                                                      \
        for (int i = 0; i < 2; i++) {                                          \
            int idx = tid + 256 * i; int n = idx >> 3; int cc = idx & 7;       \
            uint32_t so = (uint32_t)(n * 128) + (uint32_t)((cc ^ (n & 7)) << 4); \
            size_t go = (size_t)n * HID + (ks) * KS + cc * 8;                  \
            cp16(sbase + WH_OFF + so, Wh + go);                                \
            cp16(sbase + WL_OFF + so, Wl + go);                                \
        }                                                                      \
        CP_COMMIT();                                                           \
    } while (0)

    LOAD_SLAB(0, 0);

#pragma unroll 1
    for (int ks = 0; ks < NSLAB; ks++) {
        if (ks + 1 < NSLAB) {
            LOAD_SLAB((ks + 1) & 1, ks + 1);
            CP_WAIT(1);
        } else {
            CP_WAIT(0);
        }
        __syncthreads();

        uint32_t abase = sb + SM_SLAB + (ks & 1) * STAGE_SZ;
#pragma unroll
        for (int k4 = 0; k4 < 4; k4++) {
            int cb = k4 * 2;   // 16B-chunk base of this k16 within the 64-wide slab
            uint32_t ah[2][4], al[2][4], wh[2][4], wl[2][4];
#pragma unroll
            for (int mt = 0; mt < 2; mt++) {
                int row = wm * 32 + mt * 16 + (lane & 15);
                int ccc = cb + (lane >> 4);
                uint32_t ad = abase + AH_OFF + row * 128 + ((ccc ^ (row & 7)) << 4);
                LDSM_X4(ah[mt][0], ah[mt][1], ah[mt][2], ah[mt][3], ad);
                LDSM_X4(al[mt][0], al[mt][1], al[mt][2], al[mt][3], ad + (AL_OFF - AH_OFF));
            }
#pragma unroll
            for (int nt = 0; nt < 2; nt++) {
                int row = wn * 32 + nt * 16 + (lane & 7) + ((lane >> 4) << 3);
                int ccc = cb + ((lane >> 3) & 1);
                uint32_t ad = abase + WH_OFF + row * 128 + ((ccc ^ (row & 7)) << 4);
                LDSM_X4(wh[nt][0], wh[nt][1], wh[nt][2], wh[nt][3], ad);
                LDSM_X4(wl[nt][0], wl[nt][1], wl[nt][2], wl[nt][3], ad + (WL_OFF - WH_OFF));
            }
            // x4 W result: regs {b0(n0-7), b1(n0-7), b0(n8-15), b1(n8-15)}
#pragma unroll
            for (int mt = 0; mt < 2; mt++) {
#pragma unroll
                for (int j = 0; j < 4; j++) {
                    uint32_t bh0 = wh[j >> 1][(j & 1) * 2], bh1 = wh[j >> 1][(j & 1) * 2 + 1];
                    uint32_t bl0 = wl[j >> 1][(j & 1) * 2], bl1 = wl[j >> 1][(j & 1) * 2 + 1];
                    MMA16816(c[mt][j][0], c[mt][j][1], c[mt][j][2], c[mt][j][3],
                             ah[mt][0], ah[mt][1], ah[mt][2], ah[mt][3], bh0, bh1);
                    MMA16816(c[mt][j][0], c[mt][j][1], c[mt][j][2], c[mt][j][3],
                             al[mt][0], al[mt][1], al[mt][2], al[mt][3], bh0, bh1);
                    MMA16816(c[mt][j][0], c[mt][j][1], c[mt][j][2], c[mt][j][3],
                             ah[mt][0], ah[mt][1], ah[mt][2], ah[mt][3], bl0, bl1);
                }
            }
        }
        __syncthreads();
    }
#undef LOAD_SLAB

    // ---- epilogue: + whx*x + bh, tanh, bf16 hi/lo split, store ----
    const float* xs   = (const float*)(smem + SM_XS);
    const float* whxs = (const float*)(smem + SM_WHX);
    const float* bhs  = (const float*)(smem + SM_BH);
    __nv_bfloat16* Dh = g_hTh[dst];
    __nv_bfloat16* Dl = g_hTl[dst];
    int g = lane >> 2, tg = lane & 3;

#pragma unroll
    for (int mt = 0; mt < 2; mt++) {
#pragma unroll
        for (int half = 0; half < 2; half++) {
            int rloc = wm * 32 + mt * 16 + g + half * 8;
            float xv = xs[rloc];
            size_t rowbase = (size_t)(bt0 + rloc) * HID + n0;
#pragma unroll
            for (int j = 0; j < 4; j++) {
                int nloc = wn * 32 + j * 8 + 2 * tg;
                float v0 = c[mt][j][half * 2 + 0] + whxs[nloc] * xv + bhs[nloc];
                float v1 = c[mt][j][half * 2 + 1] + whxs[nloc + 1] * xv + bhs[nloc + 1];
                float t0 = tanhf(v0), t1 = tanhf(v1);
                __nv_bfloat16 h0 = __float2bfloat16(t0);
                __nv_bfloat16 h1 = __float2bfloat16(t1);
                __nv_bfloat162 hp; hp.x = h0; hp.y = h1;
                __nv_bfloat162 lp;
                lp.x = __float2bfloat16(t0 - __bfloat162float(h0));
                lp.y = __float2bfloat16(t1 - __bfloat162float(h1));
                *(__nv_bfloat162*)(Dh + rowbase + nloc) = hp;
                *(__nv_bfloat162*)(Dl + rowbase + nloc) = lp;
            }
        }
    }
}

// ================= final projection =================
__global__ __launch_bounds__(256) void rnn_proj(
    const float* __restrict__ wph, const float* __restrict__ bp,
    float* __restrict__ out, int src)
{
    int b = blockIdx.x;
    int tid = threadIdx.x;
    const __nv_bfloat16* Hh = g_hTh[src] + (size_t)b * HID;
    const __nv_bfloat16* Hl = g_hTl[src] + (size_t)b * HID;

    float acc[NCLS];
#pragma unroll
    for (int c = 0; c < NCLS; c++) acc[c] = 0.f;

    for (int k = tid; k < HID; k += 256) {
        float hv = __bfloat162float(Hh[k]) + __bfloat162float(Hl[k]);
#pragma unroll
        for (int c = 0; c < NCLS; c++)
            acc[c] = fmaf(wph[c * HID + k], hv, acc[c]);
    }

    __shared__ float red[256];
    for (int c = 0; c < NCLS; c++) {
        red[tid] = acc[c];
        __syncthreads();
        for (int s = 128; s > 0; s >>= 1) {
            if (tid < s) red[tid] += red[tid + s];
            __syncthreads();
        }
        if (tid == 0) out[b * NCLS + c] = red[0] + bp[c];
        __syncthreads();
    }
}

extern "C" void kernel_launch(void* const* d_in, const int* in_sizes, int n_in,
                              void* d_out, int out_size) {
    const float* x   = (const float*)d_in[0];    // [512, 128]
    const float* whx = (const float*)d_in[1];    // [2048, 1]
    const float* whh = (const float*)d_in[2];    // [2048, 2048]
    const float* bh  = (const float*)d_in[3];    // [2048, 1]
    const float* wph = (const float*)d_in[4];    // [10, 2048]
    const float* bp  = (const float*)d_in[5];    // [10, 1]
    float* out = (float*)d_out;                  // [512, 10]
    (void)in_sizes; (void)n_in; (void)out_size;

    cudaFuncSetAttribute(rnn_step_mma, cudaFuncAttributeMaxDynamicSharedMemorySize, SMEM_TOTAL);

    convert_w<<<(HID * HID + 255) / 256, 256>>>(whh);
    rnn_init<<<(BATCH * HID + 255) / 256, 256>>>(whx, bh, x);

    dim3 grid(HID / BN, BATCH / BM);  // (32, 4) = 128 CTAs
    for (int t = 1; t < SEQ; t++) {
        rnn_step_mma<<<grid, 256, SMEM_TOTAL>>>(x, whx, bh, t, (t - 1) & 1, t & 1);
    }

    rnn_proj<<<BATCH, 256>>>(wph, bp, out, (SEQ - 1) & 1);  // final h in buf 1
}